// round 3
// baseline (speedup 1.0000x reference)
#include <cuda_runtime.h>
#include <cstdint>

#define NB   8
#define SQL  2048
#define SKL  2048
#define HIDN 1024
// NORM = 32 -> alpha = 1/32

// Scratch (__device__ globals per allocation-free rule)
__device__ float g_qr[(size_t)NB * SQL * HIDN];   // rounded query
__device__ float g_kr[(size_t)NB * SKL * HIDN];   // rounded key
__device__ float g_w [(size_t)3 * HIDN * HIDN];   // rounded Wq|Wk|Wv
__device__ float g_q [(size_t)NB * SQL * HIDN];   // q (tf32-rounded)
__device__ float g_k [(size_t)NB * SKL * HIDN];   // k (tf32-rounded)
__device__ float g_v [(size_t)NB * SKL * HIDN];   // v (tf32-rounded)
__device__ float g_p [(size_t)NB * SQL * SKL];    // rounded probabilities

// ---------------------------------------------------------------------------
__device__ __forceinline__ float to_tf32(float x) {
    unsigned u;
    asm("cvt.rna.tf32.f32 %0, %1;" : "=r"(u) : "f"(x));
    return __uint_as_float(u);
}

__device__ __forceinline__ void mma8(float* c, const unsigned* a, unsigned b0, unsigned b1) {
    asm volatile(
        "mma.sync.aligned.m16n8k8.row.col.f32.tf32.tf32.f32 "
        "{%0,%1,%2,%3}, {%4,%5,%6,%7}, {%8,%9}, {%0,%1,%2,%3};\n"
        : "+f"(c[0]), "+f"(c[1]), "+f"(c[2]), "+f"(c[3])
        : "r"(a[0]), "r"(a[1]), "r"(a[2]), "r"(a[3]), "r"(b0), "r"(b1));
}

__device__ __forceinline__ void cpa16(float* dst, const float* src) {
    unsigned d = (unsigned)__cvta_generic_to_shared(dst);
    asm volatile("cp.async.cg.shared.global [%0], [%1], 16;\n" :: "r"(d), "l"(src));
}
__device__ __forceinline__ void cp_commit() { asm volatile("cp.async.commit_group;\n"); }
__device__ __forceinline__ void cp_wait1()  { asm volatile("cp.async.wait_group 1;\n"); }

// ---------------------------------------------------------------------------
// GEMM  C[m,n] = sum_k A[m,k] * B[.,.]
//   BNN=0: B row-major [n][k] (NT)      BNN=1: B row-major [k][n] (NN)
//   MODE 0: C = tf32_round(acc + bias[n])
//   MODE 2: C = acc/32, mask==0 -> -inf  (fp32)
//   MODE 3: C = acc                      (fp32)
// 128x128x16 tiles, 3-stage cp.async pipeline, 8 warps, warp tile 32x64.
// ---------------------------------------------------------------------------
template<int MODE, int BNN>
__launch_bounds__(256)
__global__ void gemm_k(const float* __restrict__ Ag, const float* __restrict__ Bg,
                       const float* __restrict__ bias, const int* __restrict__ mask,
                       float* __restrict__ Cg,
                       int M, int N, int K, long sA, long sB, long sC)
{
    constexpr int BM = 128, BN = 128, BK = 16, ST = 3;
    constexpr int LDA = 20;
    constexpr int LDB = BNN ? 136 : 20;
    constexpr int ASZ = BM * LDA;                  // 2560
    constexpr int BSZ = BNN ? BK * LDB : BN * LDB; // 2176 / 2560
    extern __shared__ float sm[];
    float* Asm = sm;
    float* Bsm = sm + ST * ASZ;

    const int bz = blockIdx.z;
    Ag += (long)bz * sA;
    Bg += (long)bz * sB;
    Cg += (long)bz * sC;
    if (MODE == 2) mask += (long)bz * sC;

    const int m0 = blockIdx.y * BM;
    const int n0 = blockIdx.x * BN;
    const int t = threadIdx.x, lane = t & 31, warp = t >> 5;
    const int wm = (warp & 3) * 32;
    const int wn = (warp >> 2) * 64;
    const int g  = lane >> 2;
    const int tg = lane & 3;

    const int lr0 = t >> 2;          // 0..63
    const int lc  = (t & 3) * 4;     // 0,4,8,12

    const float* Aptr0 = Ag + (long)(m0 + lr0)      * K + lc;
    const float* Aptr1 = Ag + (long)(m0 + lr0 + 64) * K + lc;
    const float* Bptr0;
    const float* Bptr1;
    if (!BNN) {
        Bptr0 = Bg + (long)(n0 + lr0)      * K + lc;
        Bptr1 = Bg + (long)(n0 + lr0 + 64) * K + lc;
    } else {
        Bptr0 = Bg + (long)(t >> 5) * N + n0 + (t & 31) * 4;
        Bptr1 = Bptr0 + 8L * N;
    }

    float acc[2][8][4];
    #pragma unroll
    for (int i = 0; i < 2; i++)
        #pragma unroll
        for (int j = 0; j < 8; j++)
            #pragma unroll
            for (int l = 0; l < 4; l++) acc[i][j][l] = 0.f;

    auto load_tile = [&](int s, int kt) {
        float* As = Asm + s * ASZ;
        float* Bs = Bsm + s * BSZ;
        const long ko = (long)kt * BK;
        cpa16(As + lr0 * LDA + lc,        Aptr0 + ko);
        cpa16(As + (lr0 + 64) * LDA + lc, Aptr1 + ko);
        if (!BNN) {
            cpa16(Bs + lr0 * LDB + lc,        Bptr0 + ko);
            cpa16(Bs + (lr0 + 64) * LDB + lc, Bptr1 + ko);
        } else {
            const long kon = ko * N;
            cpa16(Bs + (t >> 5) * LDB + (t & 31) * 4,       Bptr0 + kon);
            cpa16(Bs + ((t >> 5) + 8) * LDB + (t & 31) * 4, Bptr1 + kon);
        }
    };

    auto comp = [&](int s) {
        const float* As = Asm + s * ASZ;
        const float* Bs = Bsm + s * BSZ;
        #pragma unroll
        for (int ks = 0; ks < 2; ks++) {
            const int k0 = ks * 8;
            unsigned af[2][4];
            #pragma unroll
            for (int mt = 0; mt < 2; mt++) {
                const int r = wm + mt * 16 + g;
                af[mt][0] = __float_as_uint(As[(r    ) * LDA + k0 + tg    ]);
                af[mt][1] = __float_as_uint(As[(r + 8) * LDA + k0 + tg    ]);
                af[mt][2] = __float_as_uint(As[(r    ) * LDA + k0 + tg + 4]);
                af[mt][3] = __float_as_uint(As[(r + 8) * LDA + k0 + tg + 4]);
            }
            #pragma unroll
            for (int nt = 0; nt < 8; nt++) {
                const int rn = wn + nt * 8 + g;
                unsigned bf0, bf1;
                if (!BNN) {
                    bf0 = __float_as_uint(Bs[rn * LDB + k0 + tg    ]);
                    bf1 = __float_as_uint(Bs[rn * LDB + k0 + tg + 4]);
                } else {
                    bf0 = __float_as_uint(Bs[(k0 + tg    ) * LDB + rn]);
                    bf1 = __float_as_uint(Bs[(k0 + tg + 4) * LDB + rn]);
                }
                mma8(acc[0][nt], af[0], bf0, bf1);
                mma8(acc[1][nt], af[1], bf0, bf1);
            }
        }
    };

    const int nK = K / BK;
    load_tile(0, 0); cp_commit();
    load_tile(1, 1); cp_commit();
    cp_wait1();
    __syncthreads();

    for (int kt = 0; kt < nK; kt++) {
        const int nk = kt + 2;
        if (nk < nK) load_tile(nk % ST, nk);
        cp_commit();
        comp(kt % ST);
        cp_wait1();
        __syncthreads();
    }

    // epilogue
    const float NEG = __int_as_float(0xff800000);
    #pragma unroll
    for (int mt = 0; mt < 2; mt++) {
        #pragma unroll
        for (int nt = 0; nt < 8; nt++) {
            const int row = m0 + wm + mt * 16 + g;
            const int col = n0 + wn + nt * 8 + tg * 2;
            float* c = acc[mt][nt];
            if (MODE == 0) {
                const float bb0 = bias[col], bb1 = bias[col + 1];
                float2 v0 = make_float2(to_tf32(c[0] + bb0), to_tf32(c[1] + bb1));
                float2 v1 = make_float2(to_tf32(c[2] + bb0), to_tf32(c[3] + bb1));
                *(float2*)&Cg[(long)row       * N + col] = v0;
                *(float2*)&Cg[(long)(row + 8) * N + col] = v1;
            } else if (MODE == 2) {
                const long r0 = (long)row * N + col;
                const long r1 = (long)(row + 8) * N + col;
                const int m00 = mask[r0], m01 = mask[r0 + 1];
                const int m10 = mask[r1], m11 = mask[r1 + 1];
                const float sc = 0.03125f;
                float2 v0 = make_float2(m00 ? c[0] * sc : NEG, m01 ? c[1] * sc : NEG);
                float2 v1 = make_float2(m10 ? c[2] * sc : NEG, m11 ? c[3] * sc : NEG);
                *(float2*)&Cg[r0] = v0;
                *(float2*)&Cg[r1] = v1;
            } else {
                float2 v0 = make_float2(c[0], c[1]);
                float2 v1 = make_float2(c[2], c[3]);
                *(float2*)&Cg[(long)row       * N + col] = v0;
                *(float2*)&Cg[(long)(row + 8) * N + col] = v1;
            }
        }
    }
}

// ---------------------------------------------------------------------------
// tf32 pre-rounding (elementwise, float4)
// ---------------------------------------------------------------------------
__global__ void round_k(const float* __restrict__ in, float* __restrict__ outp, long n4) {
    long i = blockIdx.x * (long)blockDim.x + threadIdx.x;
    if (i < n4) {
        float4 v = ((const float4*)in)[i];
        v.x = to_tf32(v.x); v.y = to_tf32(v.y);
        v.z = to_tf32(v.z); v.w = to_tf32(v.w);
        ((float4*)outp)[i] = v;
    }
}

// ---------------------------------------------------------------------------
// Row softmax over SK=2048, -inf masking, fully-masked row -> zeros.
// Writes fp32 probs in place (S) and tf32-rounded copy (P).
// ---------------------------------------------------------------------------
__device__ __forceinline__ float warpRedMax(float v) {
    #pragma unroll
    for (int o = 16; o > 0; o >>= 1) v = fmaxf(v, __shfl_xor_sync(0xffffffffu, v, o));
    return v;
}
__device__ __forceinline__ float warpRedSum(float v) {
    #pragma unroll
    for (int o = 16; o > 0; o >>= 1) v += __shfl_xor_sync(0xffffffffu, v, o);
    return v;
}

__global__ void softmax_k(float* __restrict__ S, float* __restrict__ P) {
    const long row = blockIdx.x;
    float4* p4 = (float4*)(S + row * (long)SKL);
    float4* q4 = (float4*)(P + row * (long)SKL);
    const int t = threadIdx.x;
    __shared__ float red[8];

    float4 v0 = p4[t], v1 = p4[t + 256];
    float m = fmaxf(fmaxf(fmaxf(v0.x, v0.y), fmaxf(v0.z, v0.w)),
                    fmaxf(fmaxf(v1.x, v1.y), fmaxf(v1.z, v1.w)));
    m = warpRedMax(m);
    if ((t & 31) == 0) red[t >> 5] = m;
    __syncthreads();
    m = red[0];
    #pragma unroll
    for (int i = 1; i < 8; i++) m = fmaxf(m, red[i]);
    __syncthreads();

    if (m == __int_as_float(0xff800000)) {
        float4 z = make_float4(0.f, 0.f, 0.f, 0.f);
        p4[t] = z; p4[t + 256] = z;
        q4[t] = z; q4[t + 256] = z;
        return;
    }

    v0.x = __expf(v0.x - m); v0.y = __expf(v0.y - m);
    v0.z = __expf(v0.z - m); v0.w = __expf(v0.w - m);
    v1.x = __expf(v1.x - m); v1.y = __expf(v1.y - m);
    v1.z = __expf(v1.z - m); v1.w = __expf(v1.w - m);

    float s = v0.x + v0.y + v0.z + v0.w + v1.x + v1.y + v1.z + v1.w;
    s = warpRedSum(s);
    if ((t & 31) == 0) red[t >> 5] = s;
    __syncthreads();
    s = red[0];
    #pragma unroll
    for (int i = 1; i < 8; i++) s += red[i];

    const float inv = 1.0f / s;
    v0.x *= inv; v0.y *= inv; v0.z *= inv; v0.w *= inv;
    v1.x *= inv; v1.y *= inv; v1.z *= inv; v1.w *= inv;
    p4[t] = v0; p4[t + 256] = v1;

    float4 r0 = make_float4(to_tf32(v0.x), to_tf32(v0.y), to_tf32(v0.z), to_tf32(v0.w));
    float4 r1 = make_float4(to_tf32(v1.x), to_tf32(v1.y), to_tf32(v1.z), to_tf32(v1.w));
    q4[t] = r0; q4[t + 256] = r1;
}

// ---------------------------------------------------------------------------
extern "C" void kernel_launch(void* const* d_in, const int* in_sizes, int n_in,
                              void* d_out, int out_size)
{
    const float* key   = (const float*)d_in[0];
    const float* query = (const float*)d_in[1];
    const int*   mask  = (const int*)  d_in[2];
    const float* Wq    = (const float*)d_in[3];
    const float* bq    = (const float*)d_in[4];
    const float* Wk    = (const float*)d_in[5];
    const float* bk    = (const float*)d_in[6];
    const float* Wv    = (const float*)d_in[7];
    const float* bv    = (const float*)d_in[8];

    float* out   = (float*)d_out;
    float* score = out + (long)NB * SQL * HIDN;

    float *qr, *kr, *w, *q, *k, *v, *p;
    cudaGetSymbolAddress((void**)&qr, g_qr);
    cudaGetSymbolAddress((void**)&kr, g_kr);
    cudaGetSymbolAddress((void**)&w,  g_w);
    cudaGetSymbolAddress((void**)&q,  g_q);
    cudaGetSymbolAddress((void**)&k,  g_k);
    cudaGetSymbolAddress((void**)&v,  g_v);
    cudaGetSymbolAddress((void**)&p,  g_p);

    const int SM_NT = 3 * (2560 + 2560) * 4;   // 61440
    const int SM_NN = 3 * (2560 + 2176) * 4;   // 56832
    cudaFuncSetAttribute((const void*)gemm_k<0,0>, cudaFuncAttributeMaxDynamicSharedMemorySize, SM_NT);
    cudaFuncSetAttribute((const void*)gemm_k<2,0>, cudaFuncAttributeMaxDynamicSharedMemorySize, SM_NT);
    cudaFuncSetAttribute((const void*)gemm_k<3,1>, cudaFuncAttributeMaxDynamicSharedMemorySize, SM_NN);

    dim3 blk(256);

    // tf32 pre-rounding
    const long n4qk = (long)NB * SQL * HIDN / 4;     // 4,194,304
    const long n4w  = (long)HIDN * HIDN / 4;         // 262,144
    round_k<<<(unsigned)((n4qk + 255) / 256), blk>>>(query, qr, n4qk);
    round_k<<<(unsigned)((n4qk + 255) / 256), blk>>>(key,   kr, n4qk);
    round_k<<<(unsigned)((n4w + 255) / 256),  blk>>>(Wq, w,                    n4w);
    round_k<<<(unsigned)((n4w + 255) / 256),  blk>>>(Wk, w + (long)HIDN*HIDN,   n4w);
    round_k<<<(unsigned)((n4w + 255) / 256),  blk>>>(Wv, w + 2L*HIDN*HIDN,      n4w);

    // QKV projections (NT): M=16384, N=K=1024
    dim3 gp(HIDN / 128, (NB * SQL) / 128, 1);
    gemm_k<0,0><<<gp, blk, SM_NT>>>(qr, w,                  bq, nullptr, q, NB*SQL, HIDN, HIDN, 0, 0, 0);
    gemm_k<0,0><<<gp, blk, SM_NT>>>(kr, w + (long)HIDN*HIDN, bk, nullptr, k, NB*SKL, HIDN, HIDN, 0, 0, 0);
    gemm_k<0,0><<<gp, blk, SM_NT>>>(kr, w + 2L*HIDN*HIDN,    bv, nullptr, v, NB*SKL, HIDN, HIDN, 0, 0, 0);

    // Scores (NT, per batch): S = (Q K^T)/32, mask -> -inf
    dim3 gs(SKL / 128, SQL / 128, NB);
    gemm_k<2,0><<<gs, blk, SM_NT>>>(q, k, nullptr, mask, score, SQL, SKL, HIDN,
                                    (long)SQL * HIDN, (long)SKL * HIDN, (long)SQL * SKL);

    // Softmax in place + rounded copy into g_p
    softmax_k<<<NB * SQL, 256>>>(score, p);

    // Output (NN, per batch): O = P @ V
    dim3 go(HIDN / 128, SQL / 128, NB);
    gemm_k<3,1><<<go, blk, SM_NN>>>(p, v, nullptr, nullptr, out, SQL, HIDN, SKL,
                                    (long)SQL * SKL, (long)SKL * HIDN, (long)SQL * HIDN);
}

// round 5
// speedup vs baseline: 1.5606x; 1.5606x over previous
#include <cuda_runtime.h>
#include <cuda_fp16.h>
#include <cstdint>

#define NB   8
#define SQL  2048
#define SKL  2048
#define HIDN 1024
// NORM = 32 -> alpha = 1/32

// Scratch (__device__ globals per allocation-free rule). All fp16 GEMM
// operands live in "interleaved-16" layout along their K dimension:
// within each 16-half block, halves are stored [0,1,8,9,2,3,10,11,4,5,12,13,6,7,14,15]
// so that mma.m16n8k16 fragments are contiguous 8B chunks in smem.
__device__ __align__(16) __half g_xq[(size_t)NB * SQL * HIDN];  // query fp16 (ilv)
__device__ __align__(16) __half g_xk[(size_t)NB * SKL * HIDN];  // key   fp16 (ilv)
__device__ __align__(16) __half g_w [(size_t)3 * HIDN * HIDN];  // Wq|Wk|Wv fp16 (ilv)
__device__ __align__(16) __half g_q [(size_t)NB * SQL * HIDN];  // q fp16 (ilv)
__device__ __align__(16) __half g_k [(size_t)NB * SKL * HIDN];  // k fp16 (ilv)
__device__ __align__(16) __half g_v [(size_t)NB * SKL * HIDN];  // v fp16 (PLAIN)
__device__ __align__(16) __half g_vt[(size_t)NB * HIDN * SKL];  // v^T [b][h][sk] fp16 (ilv)
__device__ __align__(16) __half g_p [(size_t)NB * SQL * SKL];   // probs fp16 (ilv)

// logical half index -> physical half index (interleave within 16-block)
__device__ __forceinline__ int ilv16(int k) {
    const int blk = k >> 4, kk = k & 15;
    const int p = kk >> 1, lo = kk & 1;
    const int w = (p < 4) ? (2 * p) : (2 * (p - 4) + 1);
    return blk * 16 + 2 * w + lo;
}

__device__ __forceinline__ void mma16(float* c, unsigned a0, unsigned a1,
                                      unsigned a2, unsigned a3,
                                      unsigned b0, unsigned b1) {
    asm volatile(
        "mma.sync.aligned.m16n8k16.row.col.f32.f16.f16.f32 "
        "{%0,%1,%2,%3}, {%4,%5,%6,%7}, {%8,%9}, {%0,%1,%2,%3};\n"
        : "+f"(c[0]), "+f"(c[1]), "+f"(c[2]), "+f"(c[3])
        : "r"(a0), "r"(a1), "r"(a2), "r"(a3), "r"(b0), "r"(b1));
}

// ---------------------------------------------------------------------------
// fp16 NT GEMM: C[m,n] = sum_k A[m,k]*B[n,k]; A,B fp16 interleaved-16 layout.
// 128x128x16 tiles, 8 warps, warp tile 32x64, double-buffered smem (16KB),
// register prefetch distance 2.
//   MODE 0: C(half) = half(acc + bias[n]); IL=1 -> interleaved store, 0 plain
//   MODE 2: C(f32)  = acc/32; mask==0 -> -inf
//   MODE 3: C(f32)  = acc
// ---------------------------------------------------------------------------
template<int MODE, int IL>
__launch_bounds__(256, 2)
__global__ void hgemm(const __half* __restrict__ Ag, const __half* __restrict__ Bg,
                      const float* __restrict__ bias, const int* __restrict__ mask,
                      void* __restrict__ Cout,
                      int N, int K, long sA, long sB, long sC)
{
    __shared__ __align__(16) char sm[16384];   // [buf][A 4KB | B 4KB]

    const int bz = blockIdx.z;
    const __half* A = Ag + (long)bz * sA;
    const __half* B = Bg + (long)bz * sB;
    const int m0 = blockIdx.y * 128, n0 = blockIdx.x * 128;
    const int t = threadIdx.x, lane = t & 31, warp = t >> 5;
    const int wm = (warp & 3) * 32, wn = (warp >> 2) * 64;
    const int g = lane >> 2, tg = lane & 3;

    // producer mapping: thread -> (row, 16B half-block)
    const int prow = t >> 1, ph = t & 1;
    const __half* pA = A + (long)(m0 + prow) * K + ph * 8;
    const __half* pB = B + (long)(n0 + prow) * K + ph * 8;
    const int soff = prow * 32 + ph * 16;

    float acc[2][8][4];
    #pragma unroll
    for (int i = 0; i < 2; i++)
        #pragma unroll
        for (int j = 0; j < 8; j++)
            #pragma unroll
            for (int l = 0; l < 4; l++) acc[i][j][l] = 0.f;

    uint4 rA[2], rB[2];
    auto ldg = [&](int kt, int slot) {
        const long o = (long)kt * 16;
        rA[slot] = *(const uint4*)(pA + o);
        rB[slot] = *(const uint4*)(pB + o);
    };
    auto sts = [&](int buf, int slot) {
        char* base = sm + buf * 8192;
        *(uint4*)(base + soff)        = rA[slot];
        *(uint4*)(base + 4096 + soff) = rB[slot];
    };
    auto comp = [&](int buf) {
        const char* As = sm + buf * 8192;
        const char* Bs = As + 4096;
        uint2 bf[8];
        #pragma unroll
        for (int nt = 0; nt < 8; nt++)
            bf[nt] = *(const uint2*)(Bs + (wn + nt * 8 + g) * 32 + tg * 8);
        #pragma unroll
        for (int mt = 0; mt < 2; mt++) {
            const int r = wm + mt * 16 + g;
            const uint2 pa = *(const uint2*)(As + r * 32 + tg * 8);
            const uint2 pb = *(const uint2*)(As + (r + 8) * 32 + tg * 8);
            #pragma unroll
            for (int nt = 0; nt < 8; nt++)
                mma16(acc[mt][nt], pa.x, pb.x, pa.y, pb.y, bf[nt].x, bf[nt].y);
        }
    };

    const int nK = K >> 4;
    ldg(0, 0); ldg(1, 1);
    sts(0, 0);
    __syncthreads();

    for (int kt = 0; kt < nK; kt++) {
        const int cur = kt & 1;
        if (kt + 2 < nK) ldg(kt + 2, kt & 1);        // slot of consumed tile kt
        comp(cur);
        if (kt + 1 < nK) sts(cur ^ 1, (kt + 1) & 1);
        __syncthreads();
    }

    // epilogue
    const float NEG = __int_as_float(0xff800000);
    #pragma unroll
    for (int mt = 0; mt < 2; mt++) {
        #pragma unroll
        for (int nt = 0; nt < 8; nt++) {
            const int row = m0 + wm + mt * 16 + g;
            const int col = n0 + wn + nt * 8 + tg * 2;
            float* c = acc[mt][nt];
            if (MODE == 0) {
                __half* C = (__half*)Cout;
                const float2 bb = *(const float2*)&bias[col];
                const __half2 h0 = __floats2half2_rn(c[0] + bb.x, c[1] + bb.y);
                const __half2 h1 = __floats2half2_rn(c[2] + bb.x, c[3] + bb.y);
                const int cc = IL ? ilv16(col) : col;
                *(__half2*)&C[(long)row       * N + cc] = h0;
                *(__half2*)&C[(long)(row + 8) * N + cc] = h1;
            } else if (MODE == 2) {
                float* C = (float*)Cout + (long)bz * sC;
                const int* mp = mask + (long)bz * sC;
                const long r0 = (long)row * N + col;
                const long r1 = (long)(row + 8) * N + col;
                const int2 mv0 = *(const int2*)&mp[r0];
                const int2 mv1 = *(const int2*)&mp[r1];
                *(float2*)&C[r0] = make_float2(mv0.x ? c[0] * 0.03125f : NEG,
                                               mv0.y ? c[1] * 0.03125f : NEG);
                *(float2*)&C[r1] = make_float2(mv1.x ? c[2] * 0.03125f : NEG,
                                               mv1.y ? c[3] * 0.03125f : NEG);
            } else {
                float* C = (float*)Cout + (long)bz * sC;
                *(float2*)&C[(long)row       * N + col] = make_float2(c[0], c[1]);
                *(float2*)&C[(long)(row + 8) * N + col] = make_float2(c[2], c[3]);
            }
        }
    }
}

// ---------------------------------------------------------------------------
// fp32 -> fp16 with interleave-16 permutation. One thread per 16-half block.
// ---------------------------------------------------------------------------
__global__ void f2h_ilv_k(const float* __restrict__ in, __half* __restrict__ outp,
                          long nblk)
{
    const long i = blockIdx.x * (long)blockDim.x + threadIdx.x;
    if (i >= nblk) return;
    const float4 f0 = ((const float4*)in)[i * 4 + 0];
    const float4 f1 = ((const float4*)in)[i * 4 + 1];
    const float4 f2 = ((const float4*)in)[i * 4 + 2];
    const float4 f3 = ((const float4*)in)[i * 4 + 3];
    // phys word order: k(0,1) k(8,9) k(2,3) k(10,11) k(4,5) k(12,13) k(6,7) k(14,15)
    __half2 w[8];
    w[0] = __floats2half2_rn(f0.x, f0.y);
    w[1] = __floats2half2_rn(f2.x, f2.y);
    w[2] = __floats2half2_rn(f0.z, f0.w);
    w[3] = __floats2half2_rn(f2.z, f2.w);
    w[4] = __floats2half2_rn(f1.x, f1.y);
    w[5] = __floats2half2_rn(f3.x, f3.y);
    w[6] = __floats2half2_rn(f1.z, f1.w);
    w[7] = __floats2half2_rn(f3.z, f3.w);
    uint4* dst = (uint4*)(outp + i * 16);
    dst[0] = *(uint4*)&w[0];
    dst[1] = *(uint4*)&w[4];
}

// ---------------------------------------------------------------------------
// V transpose (per batch): v[b][sk][h] plain fp16 -> vt[b][h][sk] ilv fp16.
// 64x64 tiles, 256 threads.
// ---------------------------------------------------------------------------
__global__ void vtrans_k(const __half* __restrict__ v, __half* __restrict__ vt)
{
    __shared__ __half tile[64][66];
    const int b = blockIdx.z;
    const int h0 = blockIdx.x * 64, sk0 = blockIdx.y * 64;
    const int t = threadIdx.x;

    const __half* src = v + ((long)b * SKL + sk0) * HIDN + h0;
    #pragma unroll
    for (int kx = 0; kx < 8; kx++) {
        const int id = t + kx * 256;
        const int r = id >> 5, c2 = id & 31;
        *(__half2*)&tile[r][c2 * 2] = *(const __half2*)&src[(long)r * HIDN + c2 * 2];
    }
    __syncthreads();
    __half* dst = vt + ((long)b * HIDN + h0) * SKL;
    #pragma unroll
    for (int kx = 0; kx < 8; kx++) {
        const int id = t + kx * 256;
        const int r = id >> 5, c2 = id & 31;
        const __half2 o = __halves2half2(tile[c2 * 2][r], tile[c2 * 2 + 1][r]);
        *(__half2*)&dst[(long)r * SKL + ilv16(sk0 + c2 * 2)] = o;
    }
}

// ---------------------------------------------------------------------------
// Row softmax over SK=2048; -inf mask; fully-masked row -> zeros.
// In-place fp32 S + interleaved fp16 copy P.
// ---------------------------------------------------------------------------
__device__ __forceinline__ float warpRedMax(float v) {
    #pragma unroll
    for (int o = 16; o > 0; o >>= 1) v = fmaxf(v, __shfl_xor_sync(0xffffffffu, v, o));
    return v;
}
__device__ __forceinline__ float warpRedSum(float v) {
    #pragma unroll
    for (int o = 16; o > 0; o >>= 1) v += __shfl_xor_sync(0xffffffffu, v, o);
    return v;
}

__global__ void softmax_k(float* __restrict__ S, __half* __restrict__ P) {
    const long row = blockIdx.x;
    float4* p4 = (float4*)(S + row * (long)SKL);
    __half* pr = P + row * (long)SKL;
    const int t = threadIdx.x;
    __shared__ float red[8];

    float4 v0 = p4[t], v1 = p4[t + 256];
    float m = fmaxf(fmaxf(fmaxf(v0.x, v0.y), fmaxf(v0.z, v0.w)),
                    fmaxf(fmaxf(v1.x, v1.y), fmaxf(v1.z, v1.w)));
    m = warpRedMax(m);
    if ((t & 31) == 0) red[t >> 5] = m;
    __syncthreads();
    m = red[0];
    #pragma unroll
    for (int i = 1; i < 8; i++) m = fmaxf(m, red[i]);
    __syncthreads();

    const int k0 = t * 4, k1 = 1024 + t * 4;
    if (m == __int_as_float(0xff800000)) {
        const float4 z = make_float4(0.f, 0.f, 0.f, 0.f);
        p4[t] = z; p4[t + 256] = z;
        const __half2 hz = __floats2half2_rn(0.f, 0.f);
        *(__half2*)&pr[ilv16(k0)]     = hz;
        *(__half2*)&pr[ilv16(k0 + 2)] = hz;
        *(__half2*)&pr[ilv16(k1)]     = hz;
        *(__half2*)&pr[ilv16(k1 + 2)] = hz;
        return;
    }

    v0.x = __expf(v0.x - m); v0.y = __expf(v0.y - m);
    v0.z = __expf(v0.z - m); v0.w = __expf(v0.w - m);
    v1.x = __expf(v1.x - m); v1.y = __expf(v1.y - m);
    v1.z = __expf(v1.z - m); v1.w = __expf(v1.w - m);

    float s = v0.x + v0.y + v0.z + v0.w + v1.x + v1.y + v1.z + v1.w;
    s = warpRedSum(s);
    if ((t & 31) == 0) red[t >> 5] = s;
    __syncthreads();
    s = red[0];
    #pragma unroll
    for (int i = 1; i < 8; i++) s += red[i];

    const float inv = 1.0f / s;
    v0.x *= inv; v0.y *= inv; v0.z *= inv; v0.w *= inv;
    v1.x *= inv; v1.y *= inv; v1.z *= inv; v1.w *= inv;
    p4[t] = v0; p4[t + 256] = v1;

    *(__half2*)&pr[ilv16(k0)]     = __floats2half2_rn(v0.x, v0.y);
    *(__half2*)&pr[ilv16(k0 + 2)] = __floats2half2_rn(v0.z, v0.w);
    *(__half2*)&pr[ilv16(k1)]     = __floats2half2_rn(v1.x, v1.y);
    *(__half2*)&pr[ilv16(k1 + 2)] = __floats2half2_rn(v1.z, v1.w);
}

// ---------------------------------------------------------------------------
extern "C" void kernel_launch(void* const* d_in, const int* in_sizes, int n_in,
                              void* d_out, int out_size)
{
    const float* key   = (const float*)d_in[0];
    const float* query = (const float*)d_in[1];
    const int*   mask  = (const int*)  d_in[2];
    const float* Wq    = (const float*)d_in[3];
    const float* bq    = (const float*)d_in[4];
    const float* Wk    = (const float*)d_in[5];
    const float* bk    = (const float*)d_in[6];
    const float* Wv    = (const float*)d_in[7];
    const float* bv    = (const float*)d_in[8];

    float* out   = (float*)d_out;
    float* score = out + (long)NB * SQL * HIDN;

    __half *xq, *xk, *w, *q, *k, *v, *vt, *p;
    cudaGetSymbolAddress((void**)&xq, g_xq);
    cudaGetSymbolAddress((void**)&xk, g_xk);
    cudaGetSymbolAddress((void**)&w,  g_w);
    cudaGetSymbolAddress((void**)&q,  g_q);
    cudaGetSymbolAddress((void**)&k,  g_k);
    cudaGetSymbolAddress((void**)&v,  g_v);
    cudaGetSymbolAddress((void**)&vt, g_vt);
    cudaGetSymbolAddress((void**)&p,  g_p);

    dim3 blk(256);

    // fp16 conversions (interleaved-16 along K)
    const long nbqk = (long)NB * SQL * HIDN / 16;   // 524288 blocks
    const long nbw  = (long)HIDN * HIDN / 16;       // 65536
    f2h_ilv_k<<<(unsigned)((nbqk + 255) / 256), blk>>>(query, xq, nbqk);
    f2h_ilv_k<<<(unsigned)((nbqk + 255) / 256), blk>>>(key,   xk, nbqk);
    f2h_ilv_k<<<(unsigned)((nbw + 255) / 256),  blk>>>(Wq, w,                      nbw);
    f2h_ilv_k<<<(unsigned)((nbw + 255) / 256),  blk>>>(Wk, w + (long)HIDN * HIDN,  nbw);
    f2h_ilv_k<<<(unsigned)((nbw + 255) / 256),  blk>>>(Wv, w + 2L * HIDN * HIDN,   nbw);

    // QKV projections: M=16384, N=K=1024  (q,k interleaved out; v plain out)
    dim3 gp(HIDN / 128, (NB * SQL) / 128, 1);
    hgemm<0, 1><<<gp, blk>>>(xq, w,                     bq, nullptr, q, HIDN, HIDN, 0, 0, 0);
    hgemm<0, 1><<<gp, blk>>>(xk, w + (long)HIDN * HIDN, bk, nullptr, k, HIDN, HIDN, 0, 0, 0);
    hgemm<0, 0><<<gp, blk>>>(xk, w + 2L * HIDN * HIDN,  bv, nullptr, v, HIDN, HIDN, 0, 0, 0);

    // V transpose: v[b][sk][h] -> vt[b][h][sk] (interleaved along sk)
    dim3 gt(HIDN / 64, SKL / 64, NB);
    vtrans_k<<<gt, blk>>>(v, vt);

    // Scores: per batch S = (Q K^T)/32, mask -> -inf   (fp32 out)
    dim3 gs(SKL / 128, SQL / 128, NB);
    hgemm<2, 0><<<gs, blk>>>(q, k, nullptr, mask, score, SKL, HIDN,
                             (long)SQL * HIDN, (long)SKL * HIDN, (long)SQL * SKL);

    // Softmax in place + interleaved fp16 copy to g_p
    softmax_k<<<NB * SQL, 256>>>(score, p);

    // Output: per batch O = P @ V  (NT vs vt[b][h][sk])   fp32 out
    dim3 go(HIDN / 128, SQL / 128, NB);
    hgemm<3, 0><<<go, blk>>>(p, vt, nullptr, nullptr, out, HIDN, SKL,
                             (long)SQL * SKL, (long)HIDN * SKL, (long)SQL * HIDN);
}

// round 6
// speedup vs baseline: 2.2381x; 1.4341x over previous
#include <cuda_runtime.h>
#include <cuda_fp16.h>
#include <cstdint>

#define NB   8
#define SQL  2048
#define SKL  2048
#define HIDN 1024
// NORM = 32 -> alpha = 1/32

// Scratch (__device__ globals per allocation-free rule). All fp16 GEMM
// operands live in "interleaved-16" layout along their K dimension:
// within each 16-half block, halves are stored [0,1,8,9,2,3,10,11,4,5,12,13,6,7,14,15]
// so that mma.m16n8k16 fragments are contiguous 8B chunks in smem.
__device__ __align__(16) __half g_xq[(size_t)NB * SQL * HIDN];  // query fp16 (ilv)
__device__ __align__(16) __half g_xk[(size_t)NB * SKL * HIDN];  // key   fp16 (ilv)
__device__ __align__(16) __half g_w [(size_t)3 * HIDN * HIDN];  // Wq|Wk|Wv fp16 (ilv)
__device__ __align__(16) __half g_q [(size_t)NB * SQL * HIDN];  // q fp16 (ilv)
__device__ __align__(16) __half g_k [(size_t)NB * SKL * HIDN];  // k fp16 (ilv)
__device__ __align__(16) __half g_v [(size_t)NB * SKL * HIDN];  // v fp16 (PLAIN)
__device__ __align__(16) __half g_vt[(size_t)NB * HIDN * SKL];  // v^T [b][h][sk] fp16 (ilv)
__device__ __align__(16) __half g_p [(size_t)NB * SQL * SKL];   // probs fp16 (ilv)

// logical half index -> physical half index (interleave within 16-block)
__device__ __forceinline__ int ilv16(int k) {
    const int blk = k >> 4, kk = k & 15;
    const int p = kk >> 1, lo = kk & 1;
    const int w = (p < 4) ? (2 * p) : (2 * (p - 4) + 1);
    return blk * 16 + 2 * w + lo;
}

__device__ __forceinline__ void mma16(float* c, unsigned a0, unsigned a1,
                                      unsigned a2, unsigned a3,
                                      unsigned b0, unsigned b1) {
    asm volatile(
        "mma.sync.aligned.m16n8k16.row.col.f32.f16.f16.f32 "
        "{%0,%1,%2,%3}, {%4,%5,%6,%7}, {%8,%9}, {%0,%1,%2,%3};\n"
        : "+f"(c[0]), "+f"(c[1]), "+f"(c[2]), "+f"(c[3])
        : "r"(a0), "r"(a1), "r"(a2), "r"(a3), "r"(b0), "r"(b1));
}

// ---------------------------------------------------------------------------
// fp16 NT GEMM: C[m,n] = sum_k A[m,k]*B[n,k]; A,B fp16 interleaved-16 layout.
// 128x128 CTA tile, BK=32 per sync (two independent 16-K sub-tiles with the
// proven 128x16 / 32B-row smem layout each -> bank behavior unchanged).
// 8 warps, warp tile 32x64, double-buffered smem (32KB), prefetch dist 1 stage.
//   MODE 0: C(half) = half(acc + bias[n]); IL=1 -> interleaved store, 0 plain
//   MODE 2: C(f32)  = acc/32; mask==0 -> -inf
//   MODE 3: C(f32)  = acc
// ---------------------------------------------------------------------------
template<int MODE, int IL>
__launch_bounds__(256, 2)
__global__ void hgemm(const __half* __restrict__ Ag, const __half* __restrict__ Bg,
                      const float* __restrict__ bias, const int* __restrict__ mask,
                      void* __restrict__ Cout,
                      int N, int K, long sA, long sB, long sC)
{
    __shared__ __align__(16) char sm[32768];   // [buf][A0 4K|A1 4K|B0 4K|B1 4K]

    const int bz = blockIdx.z;
    const __half* A = Ag + (long)bz * sA;
    const __half* B = Bg + (long)bz * sB;
    const int m0 = blockIdx.y * 128, n0 = blockIdx.x * 128;
    const int t = threadIdx.x, lane = t & 31, warp = t >> 5;
    const int wm = (warp & 3) * 32, wn = (warp >> 2) * 64;
    const int g = lane >> 2, tg = lane & 3;

    // producer mapping: thread -> (row, 16B half-block within 16-K sub-tile)
    const int prow = t >> 1, ph = t & 1;
    const __half* pA = A + (long)(m0 + prow) * K + ph * 8;
    const __half* pB = B + (long)(n0 + prow) * K + ph * 8;
    const int soff = prow * 32 + ph * 16;     // bytes within a 4KB sub-tile

    float acc[2][8][4];
    #pragma unroll
    for (int i = 0; i < 2; i++)
        #pragma unroll
        for (int j = 0; j < 8; j++)
            #pragma unroll
            for (int l = 0; l < 4; l++) acc[i][j][l] = 0.f;

    uint4 rA0, rA1, rB0, rB1;
    auto ldg = [&](int kt) {                  // kt indexes 32-K stages
        const long o = (long)kt * 32;
        rA0 = *(const uint4*)(pA + o);
        rA1 = *(const uint4*)(pA + o + 16);
        rB0 = *(const uint4*)(pB + o);
        rB1 = *(const uint4*)(pB + o + 16);
    };
    auto sts = [&](int buf) {
        char* base = sm + buf * 16384;
        *(uint4*)(base +         soff) = rA0;
        *(uint4*)(base +  4096 + soff) = rA1;
        *(uint4*)(base +  8192 + soff) = rB0;
        *(uint4*)(base + 12288 + soff) = rB1;
    };
    auto comp16 = [&](const char* As, const char* Bs) {
        uint2 bf[8];
        #pragma unroll
        for (int nt = 0; nt < 8; nt++)
            bf[nt] = *(const uint2*)(Bs + (wn + nt * 8 + g) * 32 + tg * 8);
        #pragma unroll
        for (int mt = 0; mt < 2; mt++) {
            const int r = wm + mt * 16 + g;
            const uint2 pa = *(const uint2*)(As + r * 32 + tg * 8);
            const uint2 pb = *(const uint2*)(As + (r + 8) * 32 + tg * 8);
            #pragma unroll
            for (int nt = 0; nt < 8; nt++)
                mma16(acc[mt][nt], pa.x, pb.x, pa.y, pb.y, bf[nt].x, bf[nt].y);
        }
    };
    auto comp = [&](int buf) {
        const char* base = sm + buf * 16384;
        comp16(base,        base + 8192);     // sub-tile 0
        comp16(base + 4096, base + 12288);    // sub-tile 1
    };

    const int nK = K >> 5;                    // 32-K stages
    ldg(0); sts(0);
    __syncthreads();

    for (int kt = 0; kt < nK; kt++) {
        const int cur = kt & 1;
        if (kt + 1 < nK) ldg(kt + 1);
        comp(cur);
        if (kt + 1 < nK) sts(cur ^ 1);
        __syncthreads();
    }

    // epilogue
    const float NEG = __int_as_float(0xff800000);
    #pragma unroll
    for (int mt = 0; mt < 2; mt++) {
        #pragma unroll
        for (int nt = 0; nt < 8; nt++) {
            const int row = m0 + wm + mt * 16 + g;
            const int col = n0 + wn + nt * 8 + tg * 2;
            float* c = acc[mt][nt];
            if (MODE == 0) {
                __half* C = (__half*)Cout;
                const float2 bb = *(const float2*)&bias[col];
                const __half2 h0 = __floats2half2_rn(c[0] + bb.x, c[1] + bb.y);
                const __half2 h1 = __floats2half2_rn(c[2] + bb.x, c[3] + bb.y);
                const int cc = IL ? ilv16(col) : col;
                *(__half2*)&C[(long)row       * N + cc] = h0;
                *(__half2*)&C[(long)(row + 8) * N + cc] = h1;
            } else if (MODE == 2) {
                float* C = (float*)Cout + (long)bz * sC;
                const int* mp = mask + (long)bz * sC;
                const long r0 = (long)row * N + col;
                const long r1 = (long)(row + 8) * N + col;
                const int2 mv0 = *(const int2*)&mp[r0];
                const int2 mv1 = *(const int2*)&mp[r1];
                *(float2*)&C[r0] = make_float2(mv0.x ? c[0] * 0.03125f : NEG,
                                               mv0.y ? c[1] * 0.03125f : NEG);
                *(float2*)&C[r1] = make_float2(mv1.x ? c[2] * 0.03125f : NEG,
                                               mv1.y ? c[3] * 0.03125f : NEG);
            } else {
                float* C = (float*)Cout + (long)bz * sC;
                *(float2*)&C[(long)row       * N + col] = make_float2(c[0], c[1]);
                *(float2*)&C[(long)(row + 8) * N + col] = make_float2(c[2], c[3]);
            }
        }
    }
}

// ---------------------------------------------------------------------------
// fp32 -> fp16 with interleave-16 permutation. One thread per 16-half block.
// ---------------------------------------------------------------------------
__global__ void f2h_ilv_k(const float* __restrict__ in, __half* __restrict__ outp,
                          long nblk)
{
    const long i = blockIdx.x * (long)blockDim.x + threadIdx.x;
    if (i >= nblk) return;
    const float4 f0 = ((const float4*)in)[i * 4 + 0];
    const float4 f1 = ((const float4*)in)[i * 4 + 1];
    const float4 f2 = ((const float4*)in)[i * 4 + 2];
    const float4 f3 = ((const float4*)in)[i * 4 + 3];
    // phys word order: k(0,1) k(8,9) k(2,3) k(10,11) k(4,5) k(12,13) k(6,7) k(14,15)
    __half2 w[8];
    w[0] = __floats2half2_rn(f0.x, f0.y);
    w[1] = __floats2half2_rn(f2.x, f2.y);
    w[2] = __floats2half2_rn(f0.z, f0.w);
    w[3] = __floats2half2_rn(f2.z, f2.w);
    w[4] = __floats2half2_rn(f1.x, f1.y);
    w[5] = __floats2half2_rn(f3.x, f3.y);
    w[6] = __floats2half2_rn(f1.z, f1.w);
    w[7] = __floats2half2_rn(f3.z, f3.w);
    uint4* dst = (uint4*)(outp + i * 16);
    dst[0] = *(uint4*)&w[0];
    dst[1] = *(uint4*)&w[4];
}

// ---------------------------------------------------------------------------
// V transpose (per batch): v[b][sk][h] plain fp16 -> vt[b][h][sk] ilv fp16.
// 64x64 tiles, 256 threads.
// ---------------------------------------------------------------------------
__global__ void vtrans_k(const __half* __restrict__ v, __half* __restrict__ vt)
{
    __shared__ __half tile[64][66];
    const int b = blockIdx.z;
    const int h0 = blockIdx.x * 64, sk0 = blockIdx.y * 64;
    const int t = threadIdx.x;

    const __half* src = v + ((long)b * SKL + sk0) * HIDN + h0;
    #pragma unroll
    for (int kx = 0; kx < 8; kx++) {
        const int id = t + kx * 256;
        const int r = id >> 5, c2 = id & 31;
        *(__half2*)&tile[r][c2 * 2] = *(const __half2*)&src[(long)r * HIDN + c2 * 2];
    }
    __syncthreads();
    __half* dst = vt + ((long)b * HIDN + h0) * SKL;
    #pragma unroll
    for (int kx = 0; kx < 8; kx++) {
        const int id = t + kx * 256;
        const int r = id >> 5, c2 = id & 31;
        const __half2 o = __halves2half2(tile[c2 * 2][r], tile[c2 * 2 + 1][r]);
        *(__half2*)&dst[(long)r * SKL + ilv16(sk0 + c2 * 2)] = o;
    }
}

// ---------------------------------------------------------------------------
// Row softmax over SK=2048; -inf mask; fully-masked row -> zeros.
// In-place fp32 S + interleaved fp16 copy P.
// ---------------------------------------------------------------------------
__device__ __forceinline__ float warpRedMax(float v) {
    #pragma unroll
    for (int o = 16; o > 0; o >>= 1) v = fmaxf(v, __shfl_xor_sync(0xffffffffu, v, o));
    return v;
}
__device__ __forceinline__ float warpRedSum(float v) {
    #pragma unroll
    for (int o = 16; o > 0; o >>= 1) v += __shfl_xor_sync(0xffffffffu, v, o);
    return v;
}

__global__ void softmax_k(float* __restrict__ S, __half* __restrict__ P) {
    const long row = blockIdx.x;
    float4* p4 = (float4*)(S + row * (long)SKL);
    __half* pr = P + row * (long)SKL;
    const int t = threadIdx.x;
    __shared__ float red[8];

    float4 v0 = p4[t], v1 = p4[t + 256];
    float m = fmaxf(fmaxf(fmaxf(v0.x, v0.y), fmaxf(v0.z, v0.w)),
                    fmaxf(fmaxf(v1.x, v1.y), fmaxf(v1.z, v1.w)));
    m = warpRedMax(m);
    if ((t & 31) == 0) red[t >> 5] = m;
    __syncthreads();
    m = red[0];
    #pragma unroll
    for (int i = 1; i < 8; i++) m = fmaxf(m, red[i]);
    __syncthreads();

    const int k0 = t * 4, k1 = 1024 + t * 4;
    if (m == __int_as_float(0xff800000)) {
        const float4 z = make_float4(0.f, 0.f, 0.f, 0.f);
        p4[t] = z; p4[t + 256] = z;
        const __half2 hz = __floats2half2_rn(0.f, 0.f);
        *(__half2*)&pr[ilv16(k0)]     = hz;
        *(__half2*)&pr[ilv16(k0 + 2)] = hz;
        *(__half2*)&pr[ilv16(k1)]     = hz;
        *(__half2*)&pr[ilv16(k1 + 2)] = hz;
        return;
    }

    v0.x = __expf(v0.x - m); v0.y = __expf(v0.y - m);
    v0.z = __expf(v0.z - m); v0.w = __expf(v0.w - m);
    v1.x = __expf(v1.x - m); v1.y = __expf(v1.y - m);
    v1.z = __expf(v1.z - m); v1.w = __expf(v1.w - m);

    float s = v0.x + v0.y + v0.z + v0.w + v1.x + v1.y + v1.z + v1.w;
    s = warpRedSum(s);
    if ((t & 31) == 0) red[t >> 5] = s;
    __syncthreads();
    s = red[0];
    #pragma unroll
    for (int i = 1; i < 8; i++) s += red[i];

    const float inv = 1.0f / s;
    v0.x *= inv; v0.y *= inv; v0.z *= inv; v0.w *= inv;
    v1.x *= inv; v1.y *= inv; v1.z *= inv; v1.w *= inv;
    p4[t] = v0; p4[t + 256] = v1;

    *(__half2*)&pr[ilv16(k0)]     = __floats2half2_rn(v0.x, v0.y);
    *(__half2*)&pr[ilv16(k0 + 2)] = __floats2half2_rn(v0.z, v0.w);
    *(__half2*)&pr[ilv16(k1)]     = __floats2half2_rn(v1.x, v1.y);
    *(__half2*)&pr[ilv16(k1 + 2)] = __floats2half2_rn(v1.z, v1.w);
}

// ---------------------------------------------------------------------------
extern "C" void kernel_launch(void* const* d_in, const int* in_sizes, int n_in,
                              void* d_out, int out_size)
{
    const float* key   = (const float*)d_in[0];
    const float* query = (const float*)d_in[1];
    const int*   mask  = (const int*)  d_in[2];
    const float* Wq    = (const float*)d_in[3];
    const float* bq    = (const float*)d_in[4];
    const float* Wk    = (const float*)d_in[5];
    const float* bk    = (const float*)d_in[6];
    const float* Wv    = (const float*)d_in[7];
    const float* bv    = (const float*)d_in[8];

    float* out   = (float*)d_out;
    float* score = out + (long)NB * SQL * HIDN;

    __half *xq, *xk, *w, *q, *k, *v, *vt, *p;
    cudaGetSymbolAddress((void**)&xq, g_xq);
    cudaGetSymbolAddress((void**)&xk, g_xk);
    cudaGetSymbolAddress((void**)&w,  g_w);
    cudaGetSymbolAddress((void**)&q,  g_q);
    cudaGetSymbolAddress((void**)&k,  g_k);
    cudaGetSymbolAddress((void**)&v,  g_v);
    cudaGetSymbolAddress((void**)&vt, g_vt);
    cudaGetSymbolAddress((void**)&p,  g_p);

    dim3 blk(256);

    // fp16 conversions (interleaved-16 along K)
    const long nbqk = (long)NB * SQL * HIDN / 16;   // 524288 blocks
    const long nbw  = (long)HIDN * HIDN / 16;       // 65536
    f2h_ilv_k<<<(unsigned)((nbqk + 255) / 256), blk>>>(query, xq, nbqk);
    f2h_ilv_k<<<(unsigned)((nbqk + 255) / 256), blk>>>(key,   xk, nbqk);
    f2h_ilv_k<<<(unsigned)((nbw + 255) / 256),  blk>>>(Wq, w,                      nbw);
    f2h_ilv_k<<<(unsigned)((nbw + 255) / 256),  blk>>>(Wk, w + (long)HIDN * HIDN,  nbw);
    f2h_ilv_k<<<(unsigned)((nbw + 255) / 256),  blk>>>(Wv, w + 2L * HIDN * HIDN,   nbw);

    // QKV projections: M=16384, N=K=1024  (q,k interleaved out; v plain out)
    dim3 gp(HIDN / 128, (NB * SQL) / 128, 1);
    hgemm<0, 1><<<gp, blk>>>(xq, w,                     bq, nullptr, q, HIDN, HIDN, 0, 0, 0);
    hgemm<0, 1><<<gp, blk>>>(xk, w + (long)HIDN * HIDN, bk, nullptr, k, HIDN, HIDN, 0, 0, 0);
    hgemm<0, 0><<<gp, blk>>>(xk, w + 2L * HIDN * HIDN,  bv, nullptr, v, HIDN, HIDN, 0, 0, 0);

    // V transpose: v[b][sk][h] -> vt[b][h][sk] (interleaved along sk)
    dim3 gt(HIDN / 64, SKL / 64, NB);
    vtrans_k<<<gt, blk>>>(v, vt);

    // Scores: per batch S = (Q K^T)/32, mask -> -inf   (fp32 out)
    dim3 gs(SKL / 128, SQL / 128, NB);
    hgemm<2, 0><<<gs, blk>>>(q, k, nullptr, mask, score, SKL, HIDN,
                             (long)SQL * HIDN, (long)SKL * HIDN, (long)SQL * SKL);

    // Softmax in place + interleaved fp16 copy to g_p
    softmax_k<<<NB * SQL, 256>>>(score, p);

    // Output: per batch O = P @ V  (NT vs vt[b][h][sk])   fp32 out
    dim3 go(HIDN / 128, SQL / 128, NB);
    hgemm<3, 0><<<go, blk>>>(p, vt, nullptr, nullptr, out, HIDN, SKL,
                             (long)SQL * SKL, (long)HIDN * SKL, (long)SQL * HIDN);
}

// round 7
// speedup vs baseline: 2.5371x; 1.1336x over previous
#include <cuda_runtime.h>
#include <cuda_fp16.h>
#include <cstdint>

#define NB   8
#define SQL  2048
#define SKL  2048
#define HIDN 1024
// NORM = 32 -> alpha = 1/32

// Scratch (__device__ globals per allocation-free rule). All fp16 GEMM
// operands live in "interleaved-16" layout along their K dimension:
// within each 16-half block, halves are stored [0,1,8,9,2,3,10,11,4,5,12,13,6,7,14,15]
// so that mma.m16n8k16 fragments are contiguous 8B chunks in smem.
__device__ __align__(16) __half g_xq[(size_t)NB * SQL * HIDN];  // query fp16 (ilv)
__device__ __align__(16) __half g_xk[(size_t)NB * SKL * HIDN];  // key   fp16 (ilv)
__device__ __align__(16) __half g_w [(size_t)3 * HIDN * HIDN];  // Wq|Wk|Wv fp16 (ilv)
__device__ __align__(16) __half g_q [(size_t)NB * SQL * HIDN];  // q fp16 (ilv)
__device__ __align__(16) __half g_k [(size_t)NB * SKL * HIDN];  // k fp16 (ilv)
__device__ __align__(16) __half g_v [(size_t)NB * SKL * HIDN];  // v fp16 (PLAIN)
__device__ __align__(16) __half g_vt[(size_t)NB * HIDN * SKL];  // v^T [b][h][sk] fp16 (ilv)
__device__ __align__(16) __half g_p [(size_t)NB * SQL * SKL];   // probs fp16 (ilv)

// logical half index -> physical half index (interleave within 16-block)
__device__ __forceinline__ int ilv16(int k) {
    const int blk = k >> 4, kk = k & 15;
    const int p = kk >> 1, lo = kk & 1;
    const int w = (p < 4) ? (2 * p) : (2 * (p - 4) + 1);
    return blk * 16 + 2 * w + lo;
}

__device__ __forceinline__ void mma16(float* c, unsigned a0, unsigned a1,
                                      unsigned a2, unsigned a3,
                                      unsigned b0, unsigned b1) {
    asm volatile(
        "mma.sync.aligned.m16n8k16.row.col.f32.f16.f16.f32 "
        "{%0,%1,%2,%3}, {%4,%5,%6,%7}, {%8,%9}, {%0,%1,%2,%3};\n"
        : "+f"(c[0]), "+f"(c[1]), "+f"(c[2]), "+f"(c[3])
        : "r"(a0), "r"(a1), "r"(a2), "r"(a3), "r"(b0), "r"(b1));
}

__device__ __forceinline__ void cpa16(void* dst, const void* src) {
    unsigned d = (unsigned)__cvta_generic_to_shared(dst);
    asm volatile("cp.async.cg.shared.global [%0], [%1], 16;" :: "r"(d), "l"(src) : "memory");
}
__device__ __forceinline__ void cp_commit() { asm volatile("cp.async.commit_group;"); }
__device__ __forceinline__ void cp_wait1()  { asm volatile("cp.async.wait_group 1;"); }
__device__ __forceinline__ void cp_wait0()  { asm volatile("cp.async.wait_group 0;"); }

// ---------------------------------------------------------------------------
// fp16 NT GEMM: C[m,n] = sum_k A[m,k]*B[n,k]; A,B fp16 interleaved-16 layout.
// 128x128 CTA tile, BK=64 per sync (four independent 16-K sub-tiles with the
// proven 128x16 / 32B-row smem layout each). 8 warps, warp tile 32x64.
// 3-stage cp.async ring (3 x 32KB smem), 1 syncthreads per 64-K iteration.
//   MODE 0: C(half) = half(acc + bias[n]); IL=1 -> interleaved store, 0 plain
//   MODE 2: C(f32)  = acc/32; mask==0 -> -inf
//   MODE 3: C(f32)  = acc
// ---------------------------------------------------------------------------
template<int MODE, int IL>
__launch_bounds__(256, 2)
__global__ void hgemm(const __half* __restrict__ Ag, const __half* __restrict__ Bg,
                      const float* __restrict__ bias, const int* __restrict__ mask,
                      void* __restrict__ Cout,
                      int N, int K, long sA, long sB, long sC)
{
    extern __shared__ __align__(16) char sm[];   // 3 stages x [A 16KB | B 16KB]

    const int bz = blockIdx.z;
    const __half* A = Ag + (long)bz * sA;
    const __half* B = Bg + (long)bz * sB;
    const int m0 = blockIdx.y * 128, n0 = blockIdx.x * 128;
    const int t = threadIdx.x, lane = t & 31, warp = t >> 5;
    const int wm = (warp & 3) * 32, wn = (warp >> 2) * 64;
    const int g = lane >> 2, tg = lane & 3;

    // producer mapping: thread -> row (t>>1); 4 chunk-pairs; lane-pairs cover
    // one aligned 32B sector per cp.async instruction.
    const int prow = t >> 1, ph = t & 1;
    const __half* pA = A + (long)(m0 + prow) * K + ph * 8;
    const __half* pB = B + (long)(n0 + prow) * K + ph * 8;
    const int soff = prow * 32 + ph * 16;     // bytes within a 4KB sub-tile

    float acc[2][8][4];
    #pragma unroll
    for (int i = 0; i < 2; i++)
        #pragma unroll
        for (int j = 0; j < 8; j++)
            #pragma unroll
            for (int l = 0; l < 4; l++) acc[i][j][l] = 0.f;

    auto load_stage = [&](int st, int kt) {   // kt indexes 64-K stages
        char* base = sm + st * 32768;
        const long ko = (long)kt * 64;
        #pragma unroll
        for (int s = 0; s < 4; s++) {         // sub-tile s covers k [16s,16s+16)
            cpa16(base +         s * 4096 + soff, pA + ko + s * 16);
            cpa16(base + 16384 + s * 4096 + soff, pB + ko + s * 16);
        }
    };
    auto comp16 = [&](const char* As, const char* Bs) {
        uint2 bf[8];
        #pragma unroll
        for (int nt = 0; nt < 8; nt++)
            bf[nt] = *(const uint2*)(Bs + (wn + nt * 8 + g) * 32 + tg * 8);
        #pragma unroll
        for (int mt = 0; mt < 2; mt++) {
            const int r = wm + mt * 16 + g;
            const uint2 pa = *(const uint2*)(As + r * 32 + tg * 8);
            const uint2 pb = *(const uint2*)(As + (r + 8) * 32 + tg * 8);
            #pragma unroll
            for (int nt = 0; nt < 8; nt++)
                mma16(acc[mt][nt], pa.x, pb.x, pa.y, pb.y, bf[nt].x, bf[nt].y);
        }
    };
    auto comp = [&](int st) {
        const char* base = sm + st * 32768;
        #pragma unroll
        for (int s = 0; s < 4; s++)
            comp16(base + s * 4096, base + 16384 + s * 4096);
    };

    const int nK = K >> 6;                    // 64-K stages
    load_stage(0, 0); cp_commit();
    load_stage(1, 1); cp_commit();
    cp_wait1();
    __syncthreads();

    int st = 0;
    for (int kt = 0; kt < nK; kt++) {
        comp(st);
        if (kt + 2 < nK) {
            int st2 = st + 2; if (st2 >= 3) st2 -= 3;
            load_stage(st2, kt + 2);
            cp_commit();
            cp_wait1();
        } else {
            cp_wait0();
        }
        __syncthreads();
        if (++st == 3) st = 0;
    }

    // epilogue
    const float NEG = __int_as_float(0xff800000);
    #pragma unroll
    for (int mt = 0; mt < 2; mt++) {
        #pragma unroll
        for (int nt = 0; nt < 8; nt++) {
            const int row = m0 + wm + mt * 16 + g;
            const int col = n0 + wn + nt * 8 + tg * 2;
            float* c = acc[mt][nt];
            if (MODE == 0) {
                __half* C = (__half*)Cout;
                const float2 bb = *(const float2*)&bias[col];
                const __half2 h0 = __floats2half2_rn(c[0] + bb.x, c[1] + bb.y);
                const __half2 h1 = __floats2half2_rn(c[2] + bb.x, c[3] + bb.y);
                const int cc = IL ? ilv16(col) : col;
                *(__half2*)&C[(long)row       * N + cc] = h0;
                *(__half2*)&C[(long)(row + 8) * N + cc] = h1;
            } else if (MODE == 2) {
                float* C = (float*)Cout + (long)bz * sC;
                const int* mp = mask + (long)bz * sC;
                const long r0 = (long)row * N + col;
                const long r1 = (long)(row + 8) * N + col;
                const int2 mv0 = *(const int2*)&mp[r0];
                const int2 mv1 = *(const int2*)&mp[r1];
                *(float2*)&C[r0] = make_float2(mv0.x ? c[0] * 0.03125f : NEG,
                                               mv0.y ? c[1] * 0.03125f : NEG);
                *(float2*)&C[r1] = make_float2(mv1.x ? c[2] * 0.03125f : NEG,
                                               mv1.y ? c[3] * 0.03125f : NEG);
            } else {
                float* C = (float*)Cout + (long)bz * sC;
                *(float2*)&C[(long)row       * N + col] = make_float2(c[0], c[1]);
                *(float2*)&C[(long)(row + 8) * N + col] = make_float2(c[2], c[3]);
            }
        }
    }
}

// ---------------------------------------------------------------------------
// fp32 -> fp16 with interleave-16 permutation. One thread per 16-half block.
// ---------------------------------------------------------------------------
__global__ void f2h_ilv_k(const float* __restrict__ in, __half* __restrict__ outp,
                          long nblk)
{
    const long i = blockIdx.x * (long)blockDim.x + threadIdx.x;
    if (i >= nblk) return;
    const float4 f0 = ((const float4*)in)[i * 4 + 0];
    const float4 f1 = ((const float4*)in)[i * 4 + 1];
    const float4 f2 = ((const float4*)in)[i * 4 + 2];
    const float4 f3 = ((const float4*)in)[i * 4 + 3];
    // phys word order: k(0,1) k(8,9) k(2,3) k(10,11) k(4,5) k(12,13) k(6,7) k(14,15)
    __half2 w[8];
    w[0] = __floats2half2_rn(f0.x, f0.y);
    w[1] = __floats2half2_rn(f2.x, f2.y);
    w[2] = __floats2half2_rn(f0.z, f0.w);
    w[3] = __floats2half2_rn(f2.z, f2.w);
    w[4] = __floats2half2_rn(f1.x, f1.y);
    w[5] = __floats2half2_rn(f3.x, f3.y);
    w[6] = __floats2half2_rn(f1.z, f1.w);
    w[7] = __floats2half2_rn(f3.z, f3.w);
    uint4* dst = (uint4*)(outp + i * 16);
    dst[0] = *(uint4*)&w[0];
    dst[1] = *(uint4*)&w[4];
}

// ---------------------------------------------------------------------------
// V transpose (per batch): v[b][sk][h] plain fp16 -> vt[b][h][sk] ilv fp16.
// 64x64 tiles, 256 threads.
// ---------------------------------------------------------------------------
__global__ void vtrans_k(const __half* __restrict__ v, __half* __restrict__ vt)
{
    __shared__ __half tile[64][66];
    const int b = blockIdx.z;
    const int h0 = blockIdx.x * 64, sk0 = blockIdx.y * 64;
    const int t = threadIdx.x;

    const __half* src = v + ((long)b * SKL + sk0) * HIDN + h0;
    #pragma unroll
    for (int kx = 0; kx < 8; kx++) {
        const int id = t + kx * 256;
        const int r = id >> 5, c2 = id & 31;
        *(__half2*)&tile[r][c2 * 2] = *(const __half2*)&src[(long)r * HIDN + c2 * 2];
    }
    __syncthreads();
    __half* dst = vt + ((long)b * HIDN + h0) * SKL;
    #pragma unroll
    for (int kx = 0; kx < 8; kx++) {
        const int id = t + kx * 256;
        const int r = id >> 5, c2 = id & 31;
        const __half2 o = __halves2half2(tile[c2 * 2][r], tile[c2 * 2 + 1][r]);
        *(__half2*)&dst[(long)r * SKL + ilv16(sk0 + c2 * 2)] = o;
    }
}

// ---------------------------------------------------------------------------
// Row softmax over SK=2048; -inf mask; fully-masked row -> zeros.
// In-place fp32 S + interleaved fp16 copy P.
// ---------------------------------------------------------------------------
__device__ __forceinline__ float warpRedMax(float v) {
    #pragma unroll
    for (int o = 16; o > 0; o >>= 1) v = fmaxf(v, __shfl_xor_sync(0xffffffffu, v, o));
    return v;
}
__device__ __forceinline__ float warpRedSum(float v) {
    #pragma unroll
    for (int o = 16; o > 0; o >>= 1) v += __shfl_xor_sync(0xffffffffu, v, o);
    return v;
}

__global__ void softmax_k(float* __restrict__ S, __half* __restrict__ P) {
    const long row = blockIdx.x;
    float4* p4 = (float4*)(S + row * (long)SKL);
    __half* pr = P + row * (long)SKL;
    const int t = threadIdx.x;
    __shared__ float red[8];

    float4 v0 = p4[t], v1 = p4[t + 256];
    float m = fmaxf(fmaxf(fmaxf(v0.x, v0.y), fmaxf(v0.z, v0.w)),
                    fmaxf(fmaxf(v1.x, v1.y), fmaxf(v1.z, v1.w)));
    m = warpRedMax(m);
    if ((t & 31) == 0) red[t >> 5] = m;
    __syncthreads();
    m = red[0];
    #pragma unroll
    for (int i = 1; i < 8; i++) m = fmaxf(m, red[i]);
    __syncthreads();

    const int k0 = t * 4, k1 = 1024 + t * 4;
    if (m == __int_as_float(0xff800000)) {
        const float4 z = make_float4(0.f, 0.f, 0.f, 0.f);
        p4[t] = z; p4[t + 256] = z;
        const __half2 hz = __floats2half2_rn(0.f, 0.f);
        *(__half2*)&pr[ilv16(k0)]     = hz;
        *(__half2*)&pr[ilv16(k0 + 2)] = hz;
        *(__half2*)&pr[ilv16(k1)]     = hz;
        *(__half2*)&pr[ilv16(k1 + 2)] = hz;
        return;
    }

    v0.x = __expf(v0.x - m); v0.y = __expf(v0.y - m);
    v0.z = __expf(v0.z - m); v0.w = __expf(v0.w - m);
    v1.x = __expf(v1.x - m); v1.y = __expf(v1.y - m);
    v1.z = __expf(v1.z - m); v1.w = __expf(v1.w - m);

    float s = v0.x + v0.y + v0.z + v0.w + v1.x + v1.y + v1.z + v1.w;
    s = warpRedSum(s);
    if ((t & 31) == 0) red[t >> 5] = s;
    __syncthreads();
    s = red[0];
    #pragma unroll
    for (int i = 1; i < 8; i++) s += red[i];

    const float inv = 1.0f / s;
    v0.x *= inv; v0.y *= inv; v0.z *= inv; v0.w *= inv;
    v1.x *= inv; v1.y *= inv; v1.z *= inv; v1.w *= inv;
    p4[t] = v0; p4[t + 256] = v1;

    *(__half2*)&pr[ilv16(k0)]     = __floats2half2_rn(v0.x, v0.y);
    *(__half2*)&pr[ilv16(k0 + 2)] = __floats2half2_rn(v0.z, v0.w);
    *(__half2*)&pr[ilv16(k1)]     = __floats2half2_rn(v1.x, v1.y);
    *(__half2*)&pr[ilv16(k1 + 2)] = __floats2half2_rn(v1.z, v1.w);
}

// ---------------------------------------------------------------------------
extern "C" void kernel_launch(void* const* d_in, const int* in_sizes, int n_in,
                              void* d_out, int out_size)
{
    const float* key   = (const float*)d_in[0];
    const float* query = (const float*)d_in[1];
    const int*   mask  = (const int*)  d_in[2];
    const float* Wq    = (const float*)d_in[3];
    const float* bq    = (const float*)d_in[4];
    const float* Wk    = (const float*)d_in[5];
    const float* bk    = (const float*)d_in[6];
    const float* Wv    = (const float*)d_in[7];
    const float* bv    = (const float*)d_in[8];

    float* out   = (float*)d_out;
    float* score = out + (long)NB * SQL * HIDN;

    __half *xq, *xk, *w, *q, *k, *v, *vt, *p;
    cudaGetSymbolAddress((void**)&xq, g_xq);
    cudaGetSymbolAddress((void**)&xk, g_xk);
    cudaGetSymbolAddress((void**)&w,  g_w);
    cudaGetSymbolAddress((void**)&q,  g_q);
    cudaGetSymbolAddress((void**)&k,  g_k);
    cudaGetSymbolAddress((void**)&v,  g_v);
    cudaGetSymbolAddress((void**)&vt, g_vt);
    cudaGetSymbolAddress((void**)&p,  g_p);

    const int SMEM = 3 * 32768;   // 96KB
    cudaFuncSetAttribute((const void*)hgemm<0,1>, cudaFuncAttributeMaxDynamicSharedMemorySize, SMEM);
    cudaFuncSetAttribute((const void*)hgemm<0,0>, cudaFuncAttributeMaxDynamicSharedMemorySize, SMEM);
    cudaFuncSetAttribute((const void*)hgemm<2,0>, cudaFuncAttributeMaxDynamicSharedMemorySize, SMEM);
    cudaFuncSetAttribute((const void*)hgemm<3,0>, cudaFuncAttributeMaxDynamicSharedMemorySize, SMEM);

    dim3 blk(256);

    // fp16 conversions (interleaved-16 along K)
    const long nbqk = (long)NB * SQL * HIDN / 16;   // 524288 blocks
    const long nbw  = (long)HIDN * HIDN / 16;       // 65536
    f2h_ilv_k<<<(unsigned)((nbqk + 255) / 256), blk>>>(query, xq, nbqk);
    f2h_ilv_k<<<(unsigned)((nbqk + 255) / 256), blk>>>(key,   xk, nbqk);
    f2h_ilv_k<<<(unsigned)((nbw + 255) / 256),  blk>>>(Wq, w,                      nbw);
    f2h_ilv_k<<<(unsigned)((nbw + 255) / 256),  blk>>>(Wk, w + (long)HIDN * HIDN,  nbw);
    f2h_ilv_k<<<(unsigned)((nbw + 255) / 256),  blk>>>(Wv, w + 2L * HIDN * HIDN,   nbw);

    // QKV projections: M=16384, N=K=1024  (q,k interleaved out; v plain out)
    dim3 gp(HIDN / 128, (NB * SQL) / 128, 1);
    hgemm<0, 1><<<gp, blk, SMEM>>>(xq, w,                     bq, nullptr, q, HIDN, HIDN, 0, 0, 0);
    hgemm<0, 1><<<gp, blk, SMEM>>>(xk, w + (long)HIDN * HIDN, bk, nullptr, k, HIDN, HIDN, 0, 0, 0);
    hgemm<0, 0><<<gp, blk, SMEM>>>(xk, w + 2L * HIDN * HIDN,  bv, nullptr, v, HIDN, HIDN, 0, 0, 0);

    // V transpose: v[b][sk][h] -> vt[b][h][sk] (interleaved along sk)
    dim3 gt(HIDN / 64, SKL / 64, NB);
    vtrans_k<<<gt, blk>>>(v, vt);

    // Scores: per batch S = (Q K^T)/32, mask -> -inf   (fp32 out)
    dim3 gs(SKL / 128, SQL / 128, NB);
    hgemm<2, 0><<<gs, blk, SMEM>>>(q, k, nullptr, mask, score, SKL, HIDN,
                                   (long)SQL * HIDN, (long)SKL * HIDN, (long)SQL * SKL);

    // Softmax in place + interleaved fp16 copy to g_p
    softmax_k<<<NB * SQL, 256>>>(score, p);

    // Output: per batch O = P @ V  (NT vs vt[b][h][sk])   fp32 out
    dim3 go(HIDN / 128, SQL / 128, NB);
    hgemm<3, 0><<<go, blk, SMEM>>>(p, vt, nullptr, nullptr, out, HIDN, SKL,
                                   (long)SQL * SKL, (long)HIDN * SKL, (long)SQL * HIDN);
}

// round 9
// speedup vs baseline: 2.5491x; 1.0047x over previous
#include <cuda_runtime.h>
#include <cuda_fp16.h>
#include <cstdint>

#define NB   8
#define SQL  2048
#define SKL  2048
#define HIDN 1024
// NORM = 32 -> alpha = 1/32

// Scratch (__device__ globals per allocation-free rule). All fp16 GEMM
// operands live in "interleaved-16" layout along their K dimension:
// within each 16-half block, halves are stored [0,1,8,9,2,3,10,11,4,5,12,13,6,7,14,15]
// so that mma.m16n8k16 fragments are contiguous 8B chunks in smem.
__device__ __align__(16) __half g_xq[(size_t)NB * SQL * HIDN];  // query fp16 (ilv)
__device__ __align__(16) __half g_xk[(size_t)NB * SKL * HIDN];  // key   fp16 (ilv)
__device__ __align__(16) __half g_w [(size_t)3 * HIDN * HIDN];  // Wq|Wk|Wv fp16 (ilv)
__device__ __align__(16) __half g_q [(size_t)NB * SQL * HIDN];  // q fp16 (ilv)
__device__ __align__(16) __half g_k [(size_t)NB * SKL * HIDN];  // k fp16 (ilv)
__device__ __align__(16) __half g_v [(size_t)NB * SKL * HIDN];  // v fp16 (PLAIN)
__device__ __align__(16) __half g_vt[(size_t)NB * HIDN * SKL];  // v^T [b][h][sk] fp16 (ilv)
__device__ __align__(16) __half g_p [(size_t)NB * SQL * SKL];   // probs fp16 (ilv)

// logical half index -> physical half index (interleave within 16-block)
__device__ __forceinline__ int ilv16(int k) {
    const int blk = k >> 4, kk = k & 15;
    const int p = kk >> 1, lo = kk & 1;
    const int w = (p < 4) ? (2 * p) : (2 * (p - 4) + 1);
    return blk * 16 + 2 * w + lo;
}

__device__ __forceinline__ void mma16(float* c, unsigned a0, unsigned a1,
                                      unsigned a2, unsigned a3,
                                      unsigned b0, unsigned b1) {
    asm volatile(
        "mma.sync.aligned.m16n8k16.row.col.f32.f16.f16.f32 "
        "{%0,%1,%2,%3}, {%4,%5,%6,%7}, {%8,%9}, {%0,%1,%2,%3};\n"
        : "+f"(c[0]), "+f"(c[1]), "+f"(c[2]), "+f"(c[3])
        : "r"(a0), "r"(a1), "r"(a2), "r"(a3), "r"(b0), "r"(b1));
}

__device__ __forceinline__ void cpa16(void* dst, const void* src) {
    unsigned d = (unsigned)__cvta_generic_to_shared(dst);
    asm volatile("cp.async.cg.shared.global [%0], [%1], 16;" :: "r"(d), "l"(src) : "memory");
}
__device__ __forceinline__ void cp_commit() { asm volatile("cp.async.commit_group;"); }
__device__ __forceinline__ void cp_wait1()  { asm volatile("cp.async.wait_group 1;"); }
__device__ __forceinline__ void cp_wait0()  { asm volatile("cp.async.wait_group 0;"); }

// ---------------------------------------------------------------------------
// GEMM core: C[m,n] = sum_k A[m,k]*B[n,k]; A,B fp16 interleaved-16 layout.
// 128x128 CTA tile, BK=64 per sync (four independent 16-K sub-tiles, proven
// 128x16 / 32B-row smem layout each). 8 warps, warp tile 32x64.
// 3-stage cp.async ring (3 x 32KB dynamic smem), 1 syncthreads per 64-K iter.
// All pointers batch-resolved by the caller; m0/n0 from blockIdx.x/y.
//   MODE 0: C(half) = half(acc + bias[n]); il!=0 -> interleaved col store
//   MODE 2: C(f32)  = acc/32; mask==0 -> -inf
//   MODE 3: C(f32)  = acc
// ---------------------------------------------------------------------------
template<int MODE>
__device__ __forceinline__ void gemm_core(
    const __half* __restrict__ A, const __half* __restrict__ B,
    const float* __restrict__ bias, const int* __restrict__ mask,
    void* __restrict__ Cout, int N, int K, int il)
{
    extern __shared__ __align__(16) char sm[];   // 3 stages x [A 16KB | B 16KB]

    const int m0 = blockIdx.y * 128, n0 = blockIdx.x * 128;
    const int t = threadIdx.x, lane = t & 31, warp = t >> 5;
    const int wm = (warp & 3) * 32, wn = (warp >> 2) * 64;
    const int g = lane >> 2, tg = lane & 3;

    // producer mapping: thread -> row (t>>1); lane-pairs cover one aligned
    // 32B sector per cp.async instruction.
    const int prow = t >> 1, ph = t & 1;
    const __half* pA = A + (long)(m0 + prow) * K + ph * 8;
    const __half* pB = B + (long)(n0 + prow) * K + ph * 8;
    const int soff = prow * 32 + ph * 16;     // bytes within a 4KB sub-tile

    float acc[2][8][4];
    #pragma unroll
    for (int i = 0; i < 2; i++)
        #pragma unroll
        for (int j = 0; j < 8; j++)
            #pragma unroll
            for (int l = 0; l < 4; l++) acc[i][j][l] = 0.f;

    auto load_stage = [&](int st, int kt) {   // kt indexes 64-K stages
        char* base = sm + st * 32768;
        const long ko = (long)kt * 64;
        #pragma unroll
        for (int s = 0; s < 4; s++) {         // sub-tile s covers k [16s,16s+16)
            cpa16(base +         s * 4096 + soff, pA + ko + s * 16);
            cpa16(base + 16384 + s * 4096 + soff, pB + ko + s * 16);
        }
    };
    auto comp16 = [&](const char* As, const char* Bs) {
        uint2 bf[8];
        #pragma unroll
        for (int nt = 0; nt < 8; nt++)
            bf[nt] = *(const uint2*)(Bs + (wn + nt * 8 + g) * 32 + tg * 8);
        #pragma unroll
        for (int mt = 0; mt < 2; mt++) {
            const int r = wm + mt * 16 + g;
            const uint2 pa = *(const uint2*)(As + r * 32 + tg * 8);
            const uint2 pb = *(const uint2*)(As + (r + 8) * 32 + tg * 8);
            #pragma unroll
            for (int nt = 0; nt < 8; nt++)
                mma16(acc[mt][nt], pa.x, pb.x, pa.y, pb.y, bf[nt].x, bf[nt].y);
        }
    };
    auto comp = [&](int st) {
        const char* base = sm + st * 32768;
        #pragma unroll
        for (int s = 0; s < 4; s++)
            comp16(base + s * 4096, base + 16384 + s * 4096);
    };

    const int nK = K >> 6;                    // 64-K stages
    load_stage(0, 0); cp_commit();
    load_stage(1, 1); cp_commit();
    cp_wait1();
    __syncthreads();

    int st = 0;
    for (int kt = 0; kt < nK; kt++) {
        comp(st);
        if (kt + 2 < nK) {
            int st2 = st + 2; if (st2 >= 3) st2 -= 3;
            load_stage(st2, kt + 2);
            cp_commit();
            cp_wait1();
        } else {
            cp_wait0();
        }
        __syncthreads();
        if (++st == 3) st = 0;
    }

    // epilogue
    const float NEG = __int_as_float(0xff800000);
    #pragma unroll
    for (int mt = 0; mt < 2; mt++) {
        #pragma unroll
        for (int nt = 0; nt < 8; nt++) {
            const int row = m0 + wm + mt * 16 + g;
            const int col = n0 + wn + nt * 8 + tg * 2;
            float* c = acc[mt][nt];
            if (MODE == 0) {
                __half* C = (__half*)Cout;
                const float2 bb = *(const float2*)&bias[col];
                const __half2 h0 = __floats2half2_rn(c[0] + bb.x, c[1] + bb.y);
                const __half2 h1 = __floats2half2_rn(c[2] + bb.x, c[3] + bb.y);
                const int cc = il ? ilv16(col) : col;
                *(__half2*)&C[(long)row       * N + cc] = h0;
                *(__half2*)&C[(long)(row + 8) * N + cc] = h1;
            } else if (MODE == 2) {
                float* C = (float*)Cout;
                const long r0 = (long)row * N + col;
                const long r1 = (long)(row + 8) * N + col;
                const int2 mv0 = *(const int2*)&mask[r0];
                const int2 mv1 = *(const int2*)&mask[r1];
                *(float2*)&C[r0] = make_float2(mv0.x ? c[0] * 0.03125f : NEG,
                                               mv0.y ? c[1] * 0.03125f : NEG);
                *(float2*)&C[r1] = make_float2(mv1.x ? c[2] * 0.03125f : NEG,
                                               mv1.y ? c[3] * 0.03125f : NEG);
            } else {
                float* C = (float*)Cout;
                *(float2*)&C[(long)row       * N + col] = make_float2(c[0], c[1]);
                *(float2*)&C[(long)(row + 8) * N + col] = make_float2(c[2], c[3]);
            }
        }
    }
}

// Batched fp32-out GEMM (score MODE 2 / output MODE 3), z = batch.
template<int MODE>
__launch_bounds__(256, 2)
__global__ void hgemm(const __half* __restrict__ Ag, const __half* __restrict__ Bg,
                      const int* __restrict__ mask, float* __restrict__ Cg,
                      int N, int K, long sA, long sB, long sC)
{
    const int bz = blockIdx.z;
    gemm_core<MODE>(Ag + (long)bz * sA, Bg + (long)bz * sB,
                    nullptr, (MODE == 2) ? (mask + (long)bz * sC) : nullptr,
                    Cg + (long)bz * sC, N, K, 0);
}

// Fused QKV projection: z=0 -> q (ilv), z=1 -> k (ilv), z=2 -> v (plain).
__launch_bounds__(256, 2)
__global__ void proj3(const __half* __restrict__ xq, const __half* __restrict__ xk,
                      const __half* __restrict__ w,
                      const float* __restrict__ bq, const float* __restrict__ bk,
                      const float* __restrict__ bv,
                      __half* __restrict__ q, __half* __restrict__ k,
                      __half* __restrict__ v)
{
    const int z = blockIdx.z;
    const __half* A = (z == 0) ? xq : xk;
    const __half* B = w + (long)z * HIDN * HIDN;
    const float* bias = (z == 0) ? bq : (z == 1) ? bk : bv;
    __half* C = (z == 0) ? q : (z == 1) ? k : v;
    gemm_core<0>(A, B, bias, nullptr, C, HIDN, HIDN, (z < 2) ? 1 : 0);
}

// ---------------------------------------------------------------------------
// fp32 -> fp16 with interleave-16 permutation. One thread per 16-half block.
// ---------------------------------------------------------------------------
__device__ __forceinline__ void f2h_blk(const float* __restrict__ in,
                                        __half* __restrict__ outp, long i)
{
    const float4 f0 = ((const float4*)in)[i * 4 + 0];
    const float4 f1 = ((const float4*)in)[i * 4 + 1];
    const float4 f2 = ((const float4*)in)[i * 4 + 2];
    const float4 f3 = ((const float4*)in)[i * 4 + 3];
    // phys word order: k(0,1) k(8,9) k(2,3) k(10,11) k(4,5) k(12,13) k(6,7) k(14,15)
    __half2 w[8];
    w[0] = __floats2half2_rn(f0.x, f0.y);
    w[1] = __floats2half2_rn(f2.x, f2.y);
    w[2] = __floats2half2_rn(f0.z, f0.w);
    w[3] = __floats2half2_rn(f2.z, f2.w);
    w[4] = __floats2half2_rn(f1.x, f1.y);
    w[5] = __floats2half2_rn(f3.x, f3.y);
    w[6] = __floats2half2_rn(f1.z, f1.w);
    w[7] = __floats2half2_rn(f3.z, f3.w);
    uint4* dst = (uint4*)(outp + i * 16);
    dst[0] = *(uint4*)&w[0];
    dst[1] = *(uint4*)&w[4];
}

// query+key fused convert: z=0 -> query->xq, z=1 -> key->xk
__global__ void f2h_qk(const float* __restrict__ query, const float* __restrict__ key,
                       __half* __restrict__ xq, __half* __restrict__ xk, long nblk)
{
    const long i = blockIdx.x * (long)blockDim.x + threadIdx.x;
    if (i >= nblk) return;
    if (blockIdx.z == 0) f2h_blk(query, xq, i);
    else                 f2h_blk(key,   xk, i);
}

// 3-weight fused convert: z selects Wq/Wk/Wv -> w + z*H*H
__global__ void f2h_w(const float* __restrict__ Wq, const float* __restrict__ Wk,
                      const float* __restrict__ Wv, __half* __restrict__ w, long nblk)
{
    const long i = blockIdx.x * (long)blockDim.x + threadIdx.x;
    if (i >= nblk) return;
    const int z = blockIdx.z;
    const float* in = (z == 0) ? Wq : (z == 1) ? Wk : Wv;
    f2h_blk(in, w + (long)z * HIDN * HIDN, i);
}

// ---------------------------------------------------------------------------
// V transpose (per batch): v[b][sk][h] plain fp16 -> vt[b][h][sk] ilv fp16.
// 64x64 tiles, 256 threads.
// ---------------------------------------------------------------------------
__global__ void vtrans_k(const __half* __restrict__ v, __half* __restrict__ vt)
{
    __shared__ __half tile[64][66];
    const int b = blockIdx.z;
    const int h0 = blockIdx.x * 64, sk0 = blockIdx.y * 64;
    const int t = threadIdx.x;

    const __half* src = v + ((long)b * SKL + sk0) * HIDN + h0;
    #pragma unroll
    for (int kx = 0; kx < 8; kx++) {
        const int id = t + kx * 256;
        const int r = id >> 5, c2 = id & 31;
        *(__half2*)&tile[r][c2 * 2] = *(const __half2*)&src[(long)r * HIDN + c2 * 2];
    }
    __syncthreads();
    __half* dst = vt + ((long)b * HIDN + h0) * SKL;
    #pragma unroll
    for (int kx = 0; kx < 8; kx++) {
        const int id = t + kx * 256;
        const int r = id >> 5, c2 = id & 31;
        const __half2 o = __halves2half2(tile[c2 * 2][r], tile[c2 * 2 + 1][r]);
        *(__half2*)&dst[(long)r * SKL + ilv16(sk0 + c2 * 2)] = o;
    }
}

// ---------------------------------------------------------------------------
// Row softmax over SK=2048; -inf mask; fully-masked row -> zeros.
// In-place fp32 S + interleaved fp16 copy P.
// ---------------------------------------------------------------------------
__device__ __forceinline__ float warpRedMax(float v) {
    #pragma unroll
    for (int o = 16; o > 0; o >>= 1) v = fmaxf(v, __shfl_xor_sync(0xffffffffu, v, o));
    return v;
}
__device__ __forceinline__ float warpRedSum(float v) {
    #pragma unroll
    for (int o = 16; o > 0; o >>= 1) v += __shfl_xor_sync(0xffffffffu, v, o);
    return v;
}

__global__ void softmax_k(float* __restrict__ S, __half* __restrict__ P) {
    const long row = blockIdx.x;
    float4* p4 = (float4*)(S + row * (long)SKL);
    __half* pr = P + row * (long)SKL;
    const int t = threadIdx.x;
    __shared__ float red[8];

    float4 v0 = p4[t], v1 = p4[t + 256];
    float m = fmaxf(fmaxf(fmaxf(v0.x, v0.y), fmaxf(v0.z, v0.w)),
                    fmaxf(fmaxf(v1.x, v1.y), fmaxf(v1.z, v1.w)));
    m = warpRedMax(m);
    if ((t & 31) == 0) red[t >> 5] = m;
    __syncthreads();
    m = red[0];
    #pragma unroll
    for (int i = 1; i < 8; i++) m = fmaxf(m, red[i]);
    __syncthreads();

    const int k0 = t * 4, k1 = 1024 + t * 4;
    if (m == __int_as_float(0xff800000)) {
        const float4 z = make_float4(0.f, 0.f, 0.f, 0.f);
        p4[t] = z; p4[t + 256] = z;
        const __half2 hz = __floats2half2_rn(0.f, 0.f);
        *(__half2*)&pr[ilv16(k0)]     = hz;
        *(__half2*)&pr[ilv16(k0 + 2)] = hz;
        *(__half2*)&pr[ilv16(k1)]     = hz;
        *(__half2*)&pr[ilv16(k1 + 2)] = hz;
        return;
    }

    v0.x = __expf(v0.x - m); v0.y = __expf(v0.y - m);
    v0.z = __expf(v0.z - m); v0.w = __expf(v0.w - m);
    v1.x = __expf(v1.x - m); v1.y = __expf(v1.y - m);
    v1.z = __expf(v1.z - m); v1.w = __expf(v1.w - m);

    float s = v0.x + v0.y + v0.z + v0.w + v1.x + v1.y + v1.z + v1.w;
    s = warpRedSum(s);
    if ((t & 31) == 0) red[t >> 5] = s;
    __syncthreads();
    s = red[0];
    #pragma unroll
    for (int i = 1; i < 8; i++) s += red[i];

    const float inv = 1.0f / s;
    v0.x *= inv; v0.y *= inv; v0.z *= inv; v0.w *= inv;
    v1.x *= inv; v1.y *= inv; v1.z *= inv; v1.w *= inv;
    p4[t] = v0; p4[t + 256] = v1;

    *(__half2*)&pr[ilv16(k0)]     = __floats2half2_rn(v0.x, v0.y);
    *(__half2*)&pr[ilv16(k0 + 2)] = __floats2half2_rn(v0.z, v0.w);
    *(__half2*)&pr[ilv16(k1)]     = __floats2half2_rn(v1.x, v1.y);
    *(__half2*)&pr[ilv16(k1 + 2)] = __floats2half2_rn(v1.z, v1.w);
}

// ---------------------------------------------------------------------------
extern "C" void kernel_launch(void* const* d_in, const int* in_sizes, int n_in,
                              void* d_out, int out_size)
{
    const float* key   = (const float*)d_in[0];
    const float* query = (const float*)d_in[1];
    const int*   mask  = (const int*)  d_in[2];
    const float* Wq    = (const float*)d_in[3];
    const float* bq    = (const float*)d_in[4];
    const float* Wk    = (const float*)d_in[5];
    const float* bk    = (const float*)d_in[6];
    const float* Wv    = (const float*)d_in[7];
    const float* bv    = (const float*)d_in[8];

    float* out   = (float*)d_out;
    float* score = out + (long)NB * SQL * HIDN;

    __half *xq, *xk, *w, *q, *k, *v, *vt, *p;
    cudaGetSymbolAddress((void**)&xq, g_xq);
    cudaGetSymbolAddress((void**)&xk, g_xk);
    cudaGetSymbolAddress((void**)&w,  g_w);
    cudaGetSymbolAddress((void**)&q,  g_q);
    cudaGetSymbolAddress((void**)&k,  g_k);
    cudaGetSymbolAddress((void**)&v,  g_v);
    cudaGetSymbolAddress((void**)&vt, g_vt);
    cudaGetSymbolAddress((void**)&p,  g_p);

    const int SMEM = 3 * 32768;   // 96KB
    cudaFuncSetAttribute((const void*)proj3,    cudaFuncAttributeMaxDynamicSharedMemorySize, SMEM);
    cudaFuncSetAttribute((const void*)hgemm<2>, cudaFuncAttributeMaxDynamicSharedMemorySize, SMEM);
    cudaFuncSetAttribute((const void*)hgemm<3>, cudaFuncAttributeMaxDynamicSharedMemorySize, SMEM);

    dim3 blk(256);

    // fp16 conversions (interleaved-16 along K), fused launches
    const long nbqk = (long)NB * SQL * HIDN / 16;   // 524288 blocks
    const long nbw  = (long)HIDN * HIDN / 16;       // 65536
    dim3 gqk((unsigned)((nbqk + 255) / 256), 1, 2);
    dim3 gw ((unsigned)((nbw + 255) / 256), 1, 3);
    f2h_qk<<<gqk, blk>>>(query, key, xq, xk, nbqk);
    f2h_w <<<gw,  blk>>>(Wq, Wk, Wv, w, nbw);

    // Fused QKV projections: one launch, z in {q,k,v}
    dim3 gp(HIDN / 128, (NB * SQL) / 128, 3);
    proj3<<<gp, blk, SMEM>>>(xq, xk, w, bq, bk, bv, q, k, v);

    // V transpose: v[b][sk][h] -> vt[b][h][sk] (interleaved along sk)
    dim3 gt(HIDN / 64, SKL / 64, NB);
    vtrans_k<<<gt, blk>>>(v, vt);

    // Scores: per batch S = (Q K^T)/32, mask -> -inf   (fp32 out)
    dim3 gs(SKL / 128, SQL / 128, NB);
    hgemm<2><<<gs, blk, SMEM>>>(q, k, mask, score, SKL, HIDN,
                                (long)SQL * HIDN, (long)SKL * HIDN, (long)SQL * SKL);

    // Softmax in place + interleaved fp16 copy to g_p
    softmax_k<<<NB * SQL, 256>>>(score, p);

    // Output: per batch O = P @ V  (NT vs vt[b][h][sk])   fp32 out
    dim3 go(HIDN / 128, SQL / 128, NB);
    hgemm<3><<<go, blk, SMEM>>>(p, vt, nullptr, out, HIDN, SKL,
                                (long)SQL * SKL, (long)HIDN * SKL, (long)SQL * HIDN);
}